// round 1
// baseline (speedup 1.0000x reference)
#include <cuda_runtime.h>
#include <math.h>

#define NPOS 128
#define CH 84
#define L_SEQ 8192
#define B_SEQ 16

// smem layout (floats)
#define AB_OFF 0       // 64*16*2 = 2048
#define SB_OFF 2048    // 16*16   = 256
#define K_OFF  2304    // 16
#define NB_OFF 2320    // 132*4   = 528
#define XS_OFF 2848    // 128*84  = 10752
#define SMEM_FLOATS 13600
#define SMEM_BYTES (SMEM_FLOATS * 4)

// Precomputed parameters (prep kernel -> main kernel)
__device__ float g_sB[16 * 16];     // softmax(emission_kernel), [q][s], padded
__device__ float g_AB[64 * 16 * 2]; // [d][q][(A',B')]
__device__ float g_K[16];           // per-state constant (log2-domain, /TEMP folded)

__global__ void prep_kernel(const float* __restrict__ ek,
                            const float* __restrict__ eek) {
    int t = threadIdx.x;
    for (int i = t; i < 16 * 16; i += blockDim.x) g_sB[i] = 0.f;
    for (int i = t; i < 64 * 32; i += blockDim.x) g_AB[i] = 0.f;
    if (t < 16) g_K[t] = 0.f;
    __syncthreads();
    if (t < 15) {
        const float kscale = (float)(1.4426950408889634 / 100.0); // log2(e)/TEMP
        const float basec  = (float)log(expm1(sqrt(0.05)));
        const float cconst = (float)(0.5 * 64.0 * log(2.0 * M_PI));
        // softmax row t
        float m = -1e30f;
        for (int s = 0; s < 15; s++) m = fmaxf(m, ek[t * 15 + s]);
        float e[15];
        float sum = 0.f;
        for (int s = 0; s < 15; s++) { e[s] = expf(ek[t * 15 + s] - m); sum += e[s]; }
        float inv = 1.f / sum;
        for (int s = 0; s < 15; s++) g_sB[t * 16 + s] = e[s] * inv;
        // MVN coefficients (expanded quadratic, log2 domain, /TEMP folded)
        float C = 0.f, ld = 0.f;
        for (int d = 0; d < 64; d++) {
            float mu = eek[t * 128 + d];
            float v  = eek[t * 128 + 64 + d] + basec;
            float sp = (v > 20.f) ? v : log1pf(expf(v)); // softplus
            float is2 = 1.f / (sp * sp);
            g_AB[(d * 16 + t) * 2 + 0] = -0.5f * is2 * kscale;
            g_AB[(d * 16 + t) * 2 + 1] = mu * is2 * kscale;
            C  = fmaf(mu * mu, is2, C);
            ld += logf(sp);
        }
        g_K[t] = (-0.5f * C - ld - cconst) * kscale;
    }
}

__device__ __forceinline__ void process_dim(const float* __restrict__ sm,
                                            int d, float x, float* tacc) {
    float x2 = x * x;
    const float* cf = sm + AB_OFF + d * 32;
#pragma unroll
    for (int h = 0; h < 8; h++) {
        float4 c4 = *(const float4*)(cf + h * 4);
        tacc[2 * h]     = fmaf(c4.x, x2, tacc[2 * h]);
        tacc[2 * h]     = fmaf(c4.y, x,  tacc[2 * h]);
        tacc[2 * h + 1] = fmaf(c4.z, x2, tacc[2 * h + 1]);
        tacc[2 * h + 1] = fmaf(c4.w, x,  tacc[2 * h + 1]);
    }
}

__global__ void __launch_bounds__(128)
emit_kernel(const float* __restrict__ inputs,
            const float* __restrict__ eh,
            float* __restrict__ out) {
    extern __shared__ float sm[];
    const int tid = threadIdx.x;
    const int b  = blockIdx.x >> 6;
    const int p0 = (blockIdx.x & 63) << 7;

    // ---- stage input tile (coalesced) ----
    const float4* in4 = (const float4*)(inputs + (size_t)(b * L_SEQ + p0) * CH);
    float4* xs4 = (float4*)(sm + XS_OFF);
#pragma unroll 4
    for (int i = tid; i < NPOS * CH / 4; i += 128) xs4[i] = in4[i];
    // ---- stage parameters ----
    for (int i = tid; i < 2048; i += 128) sm[AB_OFF + i] = g_AB[i];
    for (int i = tid; i < 256; i += 128)  sm[SB_OFF + i] = g_sB[i];
    if (tid < 16) sm[K_OFF + tid] = g_K[tid];
    __syncthreads();

    // ---- build nucleotide buffer with halo (positions p0-2 .. p0+129) ----
    float4* nb = (float4*)(sm + NB_OFF);
    for (int i = tid; i < NPOS + 4; i += 128) {
        int gl = p0 + i - 2;
        float4 nv;
        if (gl >= 0 && gl < L_SEQ) {
            int li = gl - p0;
            const float* nr;
            if (li >= 0 && li < NPOS) nr = sm + XS_OFF + li * CH + 79;
            else                      nr = inputs + (size_t)(b * L_SEQ + gl) * CH + 79;
            float n4 = nr[4];
            nv = make_float4(fmaf(0.25f, n4, nr[0]), fmaf(0.25f, n4, nr[1]),
                             fmaf(0.25f, n4, nr[2]), fmaf(0.25f, n4, nr[3]));
        } else {
            nv = make_float4(0.25f, 0.25f, 0.25f, 0.25f);
        }
        nb[i] = nv;
    }
    __syncthreads();

    // ---- per-thread compute: this thread owns position p0+tid ----
    const float* row = sm + XS_OFF + tid * CH;
    float4 a0 = *(const float4*)(row + 0);
    float4 a1 = *(const float4*)(row + 4);
    float4 a2 = *(const float4*)(row + 8);
    float4 a3 = *(const float4*)(row + 12);
    float cls[16] = {a0.x, a0.y, a0.z, a0.w, a1.x, a1.y, a1.z, a1.w,
                     a2.x, a2.y, a2.z, a2.w, a3.x, a3.y, a3.z, 0.f};

    // class_emit: 15x15 matvec with softmax(B)
    float cacc[15];
#pragma unroll
    for (int q = 0; q < 15; q++) {
        const float* br = sm + SB_OFF + q * 16;
        float acc = 0.f;
#pragma unroll
        for (int s = 0; s < 16; s += 4) {
            float4 bb = *(const float4*)(br + s);
            acc = fmaf(cls[s],     bb.x, acc);
            acc = fmaf(cls[s + 1], bb.y, acc);
            acc = fmaf(cls[s + 2], bb.z, acc);
            acc = fmaf(cls[s + 3], bb.w, acc);
        }
        cacc[q] = acc;
    }

    // MVN exponent accumulators (log2 domain), state 15 is a dummy pad
    float tacc[16];
#pragma unroll
    for (int q = 0; q < 16; q++) tacc[q] = sm[K_OFF + q];

    process_dim(sm, 0, a3.w, tacc);  // emb dim 0 = channel 15
#pragma unroll 5
    for (int j = 1; j <= 15; j++) {  // emb dims 1..60
        float4 v = *(const float4*)(row + 12 + 4 * j);
        int d = 4 * j - 3;
        process_dim(sm, d,     v.x, tacc);
        process_dim(sm, d + 1, v.y, tacc);
        process_dim(sm, d + 2, v.z, tacc);
        process_dim(sm, d + 3, v.w, tacc);
    }
    {
        float4 v = *(const float4*)(row + 76); // ch 76..79: emb 61,62,63, nuc0
        process_dim(sm, 61, v.x, tacc);
        process_dim(sm, 62, v.y, tacc);
        process_dim(sm, 63, v.z, tacc);
    }

    // ---- codon factor (separable LEFT/RIGHT dot products) ----
    float4 m2 = nb[tid];       // l-2
    float4 m1 = nb[tid + 1];   // l-1
    float4 c0 = nb[tid + 2];   // l
    float4 q1 = nb[tid + 3];   // l+1
    float4 q2 = nb[tid + 4];   // l+2
    float S_c0 = c0.x + c0.y + c0.z + c0.w;
    float S_q1 = q1.x + q1.y + q1.z + q1.w;
    float S_q2 = q2.x + q2.y + q2.z + q2.w;
    float S_m1 = m1.x + m1.y + m1.z + m1.w;
    float S_m2 = m2.x + m2.y + m2.z + m2.w;
    // LEFT (pivot-left 3mer: n0=l, n1=l+1, n2=l+2); A=.x C=.y G=.z T=.w
    float L_any   = S_c0 * S_q1 * S_q2 * (1.f / 64.f);
    float L_start = c0.x * q1.w * q2.z;          // ATG
    float L_ib    = 0.25f * S_c0 * q1.z * q2.w;  // NGT
    // RIGHT (pivot-right 3mer: n0=l-2, n1=l-1, n2=l)
    float Pall = S_m2 * S_m1 * S_c0;
    float tAA = m1.x * c0.x, tAG = m1.x * c0.z, tGA = m1.z * c0.x;
    float R_ns   = (Pall - m2.w * (tAA + tAG + tGA)) * (1.f / 61.f);
    float R_any  = Pall * (1.f / 64.f);
    float R_iep  = m2.x * m1.z * 0.25f * S_c0;   // AGN
    float R_stop = m2.w * (0.34f * tAA + 0.33f * tAG + 0.33f * tGA);

    float fullv[15] = {1.f, 1.f, 1.f, 1.f, 1.f, 1.f,
                       L_any * R_ns,  L_start * R_any, L_ib * R_any,
                       L_ib * R_ns,   L_ib * R_any,    L_any * R_iep,
                       L_any * R_iep, L_any * R_iep,   L_any * R_stop};

    // ---- end hints at sequence boundaries ----
    const int gl = p0 + tid;
    const float* hp = nullptr;
    if (gl == 0)              hp = eh + b * 30;
    else if (gl == L_SEQ - 1) hp = eh + b * 30 + 15;

    // ---- write result into own smem row (already consumed), then flush ----
    float* wrow = sm + XS_OFF + tid * CH;
#pragma unroll
    for (int q = 0; q < 15; q++) {
        float o = cacc[q] * exp2f(tacc[q]) * fullv[q];
        if (hp) o *= hp[q];
        wrow[q] = o;
    }
    __syncthreads();
    float* og = out + (size_t)(b * L_SEQ + p0) * 15;
    for (int i = tid; i < NPOS * 15; i += 128) {
        int pos = i / 15;
        int q   = i - pos * 15;
        og[i] = sm[XS_OFF + pos * CH + q];
    }
}

extern "C" void kernel_launch(void* const* d_in, const int* in_sizes, int n_in,
                              void* d_out, int out_size) {
    const float *inp = nullptr, *eh = nullptr, *ek = nullptr, *eek = nullptr;
    for (int i = 0; i < n_in; i++) {
        switch (in_sizes[i]) {
            case 11010048: inp = (const float*)d_in[i]; break; // inputs
            case 480:      eh  = (const float*)d_in[i]; break; // end_hints
            case 225:      ek  = (const float*)d_in[i]; break; // emission_kernel
            case 1920:     eek = (const float*)d_in[i]; break; // embedding_emission_kernel
        }
    }
    float* out = (float*)d_out;

    cudaFuncSetAttribute(emit_kernel, cudaFuncAttributeMaxDynamicSharedMemorySize,
                         SMEM_BYTES);

    prep_kernel<<<1, 128>>>(ek, eek);
    emit_kernel<<<(B_SEQ * L_SEQ) / NPOS, 128, SMEM_BYTES>>>(inp, eh, out);
}

// round 3
// speedup vs baseline: 1.7900x; 1.7900x over previous
#include <cuda_runtime.h>
#include <stdint.h>
#include <math.h>

#define NPOS 256          // positions per block
#define THREADS 128       // 2 positions per thread
#define CH 84
#define L_SEQ 8192
#define B_SEQ 16

// smem layout (float offsets)
#define AB_OFF 0          // 64 dims * 16 states * 2 (A,B)     = 2048
#define SB_OFF 2048       // class emit, [s][q] 16*16          = 256
#define K_OFF  2304       // 16
#define NB_OFF 2320       // 260 float4 nuc halo               = 1040
#define XS_OFF 3360       // 256 * 84 tile                     = 21504
#define SMEM_FLOATS 24864
#define SMEM_BYTES (SMEM_FLOATS * 4)

typedef unsigned long long ull;

__device__ __forceinline__ ull fma2(ull a, ull b, ull c) {
    ull d;
    asm("fma.rn.f32x2 %0, %1, %2, %3;" : "=l"(d) : "l"(a), "l"(b), "l"(c));
    return d;
}
__device__ __forceinline__ ull pk2(float lo, float hi) {
    ull d;
    asm("mov.b64 %0, {%1, %2};" : "=l"(d) : "f"(lo), "f"(hi));
    return d;
}
__device__ __forceinline__ void upk2(float& lo, float& hi, ull v) {
    asm("mov.b64 {%0, %1}, %2;" : "=f"(lo), "=f"(hi) : "l"(v));
}

__device__ __forceinline__ void cp_async16(unsigned int saddr, const void* gaddr) {
    asm volatile("cp.async.cg.shared.global [%0], [%1], 16;" :: "r"(saddr), "l"(gaddr));
}

// codon factor for one position; nbp points at nb[lp] (entry for global pos - 2)
__device__ __forceinline__ void codon_full(const float4* nbp, float* fullv) {
    float4 m2 = nbp[0], m1 = nbp[1], c0 = nbp[2], q1 = nbp[3], q2 = nbp[4];
    float S_c0 = c0.x + c0.y + c0.z + c0.w;
    float S_q1 = q1.x + q1.y + q1.z + q1.w;
    float S_q2 = q2.x + q2.y + q2.z + q2.w;
    float S_m1 = m1.x + m1.y + m1.z + m1.w;
    float S_m2 = m2.x + m2.y + m2.z + m2.w;
    float L_any   = S_c0 * S_q1 * S_q2 * (1.f / 64.f);
    float L_start = c0.x * q1.w * q2.z;           // ATG
    float L_ib    = 0.25f * S_c0 * q1.z * q2.w;   // NGT
    float Pall = S_m2 * S_m1 * S_c0;
    float tAA = m1.x * c0.x, tAG = m1.x * c0.z, tGA = m1.z * c0.x;
    float R_ns   = (Pall - m2.w * (tAA + tAG + tGA)) * (1.f / 61.f);
    float R_any  = Pall * (1.f / 64.f);
    float R_iep  = m2.x * m1.z * 0.25f * S_c0;    // AGN
    float R_stop = m2.w * (0.34f * tAA + 0.33f * tAG + 0.33f * tGA);
    fullv[0] = 1.f; fullv[1] = 1.f; fullv[2] = 1.f;
    fullv[3] = 1.f; fullv[4] = 1.f; fullv[5] = 1.f;
    fullv[6]  = L_any * R_ns;
    fullv[7]  = L_start * R_any;
    fullv[8]  = L_ib * R_any;
    fullv[9]  = L_ib * R_ns;
    fullv[10] = L_ib * R_any;
    fullv[11] = L_any * R_iep;
    fullv[12] = L_any * R_iep;
    fullv[13] = L_any * R_iep;
    fullv[14] = L_any * R_stop;
}

__global__ void __launch_bounds__(THREADS)
emit_kernel(const float* __restrict__ inputs,
            const float* __restrict__ eh,
            const float* __restrict__ ek,
            const float* __restrict__ eek,
            float* __restrict__ out) {
    extern __shared__ float sm[];
    const int tid = threadIdx.x;
    const int b  = blockIdx.x >> 5;
    const int p0 = (blockIdx.x & 31) << 8;

    // ---------------- phase 1: async tile load + inline prep ----------------
    const float4* in4 = (const float4*)(inputs + (size_t)(b * L_SEQ + p0) * CH);
    {
        unsigned int sbase = (unsigned int)__cvta_generic_to_shared(sm + XS_OFF);
#pragma unroll 6
        for (int i = tid; i < NPOS * CH / 4; i += THREADS)
            cp_async16(sbase + i * 16, in4 + i);
        asm volatile("cp.async.commit_group;");
    }

    const float kscale = (float)(1.4426950408889634 / 100.0); // log2(e)/TEMP
    const float basec  = (float)log(expm1(sqrt(0.05)));
    const float cconst = (float)(0.5 * 64.0 * log(2.0 * M_PI));

    // softmax rows of emission kernel -> SB[s][q]
    if (tid < 15) {
        int q = tid;
        float m = -1e30f;
        for (int s = 0; s < 15; s++) m = fmaxf(m, ek[q * 15 + s]);
        float e[15]; float sum = 0.f;
        for (int s = 0; s < 15; s++) { e[s] = expf(ek[q * 15 + s] - m); sum += e[s]; }
        float inv = 1.f / sum;
        for (int s = 0; s < 15; s++) sm[SB_OFF + s * 16 + q] = e[s] * inv;
    }
    if (tid >= 15 && tid < 31) {  // zero-pad column q=15 of SB
        for (int s = 0; s < 16; s++) sm[SB_OFF + s * 16 + 15] = 0.f;
    }
    // MVN coefficients: thread t = s*8+g handles dims 8g..8g+7 of state s
    if (tid < 120) {
        int s = tid >> 3, g = tid & 7;
        float Cp = 0.f, ldp = 0.f;
        for (int k = 0; k < 8; k++) {
            int d = g * 8 + k;
            float mu = eek[s * 128 + d];
            float v  = eek[s * 128 + 64 + d] + basec;
            float sp = (v > 20.f) ? v : log1pf(expf(v));
            float is2 = 1.f / (sp * sp);
            sm[AB_OFF + d * 32 + s * 2 + 0] = -0.5f * is2 * kscale;
            sm[AB_OFF + d * 32 + s * 2 + 1] = mu * is2 * kscale;
            Cp  = fmaf(mu * mu, is2, Cp);
            ldp += logf(sp);
        }
        sm[NB_OFF + tid * 2 + 0] = Cp;   // scratch (NB region, rebuilt later)
        sm[NB_OFF + tid * 2 + 1] = ldp;
    } else if (tid >= 120 && tid < 128) {
        // zero-pad state 15 coefficients: dims (tid-120)*8 .. +7
        int g = tid - 120;
        for (int k = 0; k < 8; k++) {
            int d = g * 8 + k;
            sm[AB_OFF + d * 32 + 30] = 0.f;
            sm[AB_OFF + d * 32 + 31] = 0.f;
        }
    }
    __syncthreads();
    if (tid < 15) {
        float C = 0.f, ld = 0.f;
        for (int g = 0; g < 8; g++) {
            C  += sm[NB_OFF + (tid * 8 + g) * 2 + 0];
            ld += sm[NB_OFF + (tid * 8 + g) * 2 + 1];
        }
        sm[K_OFF + tid] = (-0.5f * C - ld - cconst) * kscale;
    } else if (tid == 15) {
        sm[K_OFF + 15] = 0.f;
    }
    asm volatile("cp.async.wait_group 0;");
    __syncthreads();

    // ---------------- phase 2: nucleotide halo buffer ----------------
    float4* nb = (float4*)(sm + NB_OFF);
    for (int i = tid; i < NPOS + 4; i += THREADS) {
        int gl = p0 + i - 2;
        float4 nv;
        if (gl >= 0 && gl < L_SEQ) {
            int li = gl - p0;
            const float* nr;
            if (li >= 0 && li < NPOS) nr = sm + XS_OFF + li * CH + 79;
            else                      nr = inputs + (size_t)(b * L_SEQ + gl) * CH + 79;
            float n4 = nr[4];
            nv = make_float4(fmaf(0.25f, n4, nr[0]), fmaf(0.25f, n4, nr[1]),
                             fmaf(0.25f, n4, nr[2]), fmaf(0.25f, n4, nr[3]));
        } else {
            nv = make_float4(0.25f, 0.25f, 0.25f, 0.25f);
        }
        nb[i] = nv;
    }
    __syncthreads();

    // ---------------- phase 3: per-thread compute (2 positions) ----------------
    const float* rowA = sm + XS_OFF + tid * CH;
    const float* rowB = rowA + 128 * CH;

    // MVN accumulators: packed (sum A*x^2, sum B*x) per state, init (K,0)
    ull acc0[16], acc1[16];
#pragma unroll
    for (int q = 0; q < 16; q++) {
        float Kq = sm[K_OFF + q];
        acc0[q] = pk2(Kq, 0.f);
        acc1[q] = pk2(Kq, 0.f);
    }

#define PROC_DIM(d, xA, xB)                                            \
    {                                                                  \
        ull xa = pk2((xA) * (xA), (xA));                               \
        ull xb = pk2((xB) * (xB), (xB));                               \
        const ulonglong2* cdim =                                       \
            (const ulonglong2*)(sm + AB_OFF + (d) * 32);               \
        _Pragma("unroll")                                              \
        for (int h = 0; h < 8; h++) {                                  \
            ulonglong2 cv = cdim[h];                                   \
            acc0[2*h]   = fma2(cv.x, xa, acc0[2*h]);                   \
            acc0[2*h+1] = fma2(cv.y, xa, acc0[2*h+1]);                 \
            acc1[2*h]   = fma2(cv.x, xb, acc1[2*h]);                   \
            acc1[2*h+1] = fma2(cv.y, xb, acc1[2*h+1]);                 \
        }                                                              \
    }

    PROC_DIM(0, rowA[15], rowB[15]);
#pragma unroll 3
    for (int j = 0; j < 15; j++) {      // dims 1..60 (channels 16..75)
        float4 vA = *(const float4*)(rowA + 16 + 4 * j);
        float4 vB = *(const float4*)(rowB + 16 + 4 * j);
        int d = 4 * j + 1;
        PROC_DIM(d,     vA.x, vB.x);
        PROC_DIM(d + 1, vA.y, vB.y);
        PROC_DIM(d + 2, vA.z, vB.z);
        PROC_DIM(d + 3, vA.w, vB.w);
    }
    {
        float4 vA = *(const float4*)(rowA + 76);  // dims 61..63 (+nuc0)
        float4 vB = *(const float4*)(rowB + 76);
        PROC_DIM(61, vA.x, vB.x);
        PROC_DIM(62, vA.y, vB.y);
        PROC_DIM(63, vA.z, vB.z);
    }

    float eA[15], eB[15];
#pragma unroll
    for (int q = 0; q < 15; q++) {
        float lo, hi;
        upk2(lo, hi, acc0[q]); eA[q] = exp2f(lo + hi);
        upk2(lo, hi, acc1[q]); eB[q] = exp2f(lo + hi);
    }

    // class matvec: packed over state pairs
    ull ca[8], cb[8];
#pragma unroll
    for (int h = 0; h < 8; h++) { ca[h] = 0ull; cb[h] = 0ull; }
#pragma unroll 3
    for (int s = 0; s < 15; s++) {
        const ulonglong2* br = (const ulonglong2*)(sm + SB_OFF + s * 16);
        ulonglong2 b01 = br[0], b23 = br[1], b45 = br[2], b67 = br[3];
        float cvA = rowA[s], cvB = rowB[s];
        ull cpA = pk2(cvA, cvA), cpB = pk2(cvB, cvB);
        ca[0] = fma2(b01.x, cpA, ca[0]); ca[1] = fma2(b01.y, cpA, ca[1]);
        ca[2] = fma2(b23.x, cpA, ca[2]); ca[3] = fma2(b23.y, cpA, ca[3]);
        ca[4] = fma2(b45.x, cpA, ca[4]); ca[5] = fma2(b45.y, cpA, ca[5]);
        ca[6] = fma2(b67.x, cpA, ca[6]); ca[7] = fma2(b67.y, cpA, ca[7]);
        cb[0] = fma2(b01.x, cpB, cb[0]); cb[1] = fma2(b01.y, cpB, cb[1]);
        cb[2] = fma2(b23.x, cpB, cb[2]); cb[3] = fma2(b23.y, cpB, cb[3]);
        cb[4] = fma2(b45.x, cpB, cb[4]); cb[5] = fma2(b45.y, cpB, cb[5]);
        cb[6] = fma2(b67.x, cpB, cb[6]); cb[7] = fma2(b67.y, cpB, cb[7]);
    }
    float clA[16], clB[16];
#pragma unroll
    for (int h = 0; h < 8; h++) {
        upk2(clA[2*h], clA[2*h+1], ca[h]);
        upk2(clB[2*h], clB[2*h+1], cb[h]);
    }

    // codon factors
    float fullA[15], fullB[15];
    codon_full(nb + tid, fullA);
    codon_full(nb + tid + 128, fullB);

    // end hints
    const int glA = p0 + tid;
    const int glB = glA + 128;
    const float* hpA = nullptr;
    const float* hpB = nullptr;
    if (glA == 0)              hpA = eh + b * 30;
    else if (glA == L_SEQ - 1) hpA = eh + b * 30 + 15;
    if (glB == 0)              hpB = eh + b * 30;
    else if (glB == L_SEQ - 1) hpB = eh + b * 30 + 15;

    // write results into own rows (fully consumed), then coalesced flush
    float* wrA = sm + XS_OFF + tid * CH;
    float* wrB = wrA + 128 * CH;
#pragma unroll
    for (int q = 0; q < 15; q++) {
        float oA = clA[q] * eA[q] * fullA[q];
        float oB = clB[q] * eB[q] * fullB[q];
        if (hpA) oA *= hpA[q];
        if (hpB) oB *= hpB[q];
        wrA[q] = oA;
        wrB[q] = oB;
    }
    __syncthreads();
    float* og = out + (size_t)(b * L_SEQ + p0) * 15;
#pragma unroll 6
    for (int i = tid; i < NPOS * 15; i += THREADS) {
        int pos = i / 15;
        int q   = i - pos * 15;
        og[i] = sm[XS_OFF + pos * CH + q];
    }
}

extern "C" void kernel_launch(void* const* d_in, const int* in_sizes, int n_in,
                              void* d_out, int out_size) {
    const float *inp = nullptr, *eh = nullptr, *ek = nullptr, *eek = nullptr;
    for (int i = 0; i < n_in; i++) {
        switch (in_sizes[i]) {
            case 11010048: inp = (const float*)d_in[i]; break; // inputs
            case 480:      eh  = (const float*)d_in[i]; break; // end_hints
            case 225:      ek  = (const float*)d_in[i]; break; // emission_kernel
            case 1920:     eek = (const float*)d_in[i]; break; // embedding_emission_kernel
        }
    }
    float* out = (float*)d_out;

    cudaFuncSetAttribute(emit_kernel, cudaFuncAttributeMaxDynamicSharedMemorySize,
                         SMEM_BYTES);

    emit_kernel<<<(B_SEQ * L_SEQ) / NPOS, THREADS, SMEM_BYTES>>>(inp, eh, ek, eek, out);
}